// round 7
// baseline (speedup 1.0000x reference)
#include <cuda_runtime.h>
#include <cstdint>

#define B_ 64
#define T_ 96
#define NV 4
#define NF_ 17
#define HW_ 400
#define SIGLEN_ 306
#define KTOT_ 122400        // HW_*SIGLEN_
#define NCHUNK_ 255
#define KC_ 480             // NCHUNK_*KC_ == KTOT_

__device__ float g_sig [(size_t)B_ * HW_ * SIGLEN_];    // [b][p][s]  ~31 MB
__device__ float g_part[(size_t)NCHUNK_ * 64 * 32];

// ---------------------------------------------------------------------------
// Fused conv3x3(4->12) + shuffle feature exchange + path signature.
// Grid (4, 64): block = (5-row strip of 100 px, batch). 400 threads.
// tid = 4*pp + q: the 4 threads of pixel pp are adjacent lanes of one warp.
//   conv: thread computes channels 3q..3q+2 (+ copy ch 12+q, + time) of its
//         own pixel -> 5 register scalars; features never touch smem.
//   exchange: 17 shuffles in the 4-lane group; each value is consumed
//         IMMEDIATELY via predicated ops (d/pj update + ci select) so no
//         cur[17]/cj[9] arrays exist -> peak live regs ~125 (no spills).
//   sig: quadrant (i0,j0)=((q>>1)*8,(q&1)*8), 9x9 acc in registers.
// One __syncthreads per t (protects xs staging only).
//   lvl1_j  = p95_j - p0_j
//   lvl2_ij = 0.5*sum_t (p_t+p_{t-1})_i (p_t-p_{t-1})_j - p0_i*lvl1_j
// ---------------------------------------------------------------------------
__global__ __launch_bounds__(400, 1)
void fused_conv_sig_kernel(const float* __restrict__ x,
                           const float* __restrict__ cw,
                           const float* __restrict__ cb)
{
    __shared__ __align__(16) float xs[2][616];      // double-buffered halo (4v x 7 x 22)
    __shared__ __align__(16) float ws2[12 * 48];    // weights [k][v][12pad]
    __shared__ float wb[12];
    __shared__ float p0s[17 * 100];                 // t=0 feature snapshot

    const int cx = blockIdx.x;          // 5-row strip
    const int b  = blockIdx.y;
    const int tid = threadIdx.x;
    const int pbase = cx * 100;

    // ---- init: zero xs buffers (halo guards stay 0), repack weights ----
    for (int i = tid; i < 2 * 616; i += 400) (&xs[0][0])[i] = 0.f;
    for (int i = tid; i < 432; i += 400) {
        const int k = i / 36, r = i % 36, v = r / 9, tap = r % 9;
        ws2[k * 48 + v * 12 + tap] = cw[i];
    }
    if (tid < 12) wb[tid] = cb[tid];

    const int pp = tid >> 2, q = tid & 3;
    const int lane = tid & 31;
    const int base = lane & ~3;
    const unsigned mask4 = 0xFu << base;
    const bool ihi = (q & 2) != 0;      // i-half select
    const bool jhi = (q & 1) != 0;      // j-half select
    const int row0 = pp / 20, col0 = pp % 20;
    const int xoff = row0 * 22 + col0;
    const int k0ch = 3 * q;

    // x-staging offsets (leg A: i=tid, leg B: i=tid+400 when tid<216)
    const float* xg = x + (size_t)b * T_ * NV * HW_;
    int gofA = -1, sofA = 0, gofB = -1, sofB = 0;
    {
        const int i = tid;
        const int v = i / 154, r = i % 154, row = r / 22, col = r % 22;
        const int gr = cx * 5 - 1 + row;
        if (gr >= 0 && gr < 20 && col >= 1 && col <= 20) {
            gofA = v * HW_ + gr * 20 + (col - 1); sofA = i;
        }
    }
    if (tid < 216) {
        const int i = tid + 400;
        const int v = i / 154, r = i % 154, row = r / 22, col = r % 22;
        const int gr = cx * 5 - 1 + row;
        if (gr >= 0 && gr < 20 && col >= 1 && col <= 20) {
            gofB = v * HW_ + gr * 20 + (col - 1); sofB = i;
        }
    }

    __syncthreads();   // ws2/wb + zeroed xs visible

    const float bi0 = wb[k0ch], bi1 = wb[k0ch + 1], bi2 = wb[k0ch + 2];

    // prefetch x_0
    float rvA = 0.f, rvB = 0.f;
    if (gofA >= 0) rvA = xg[gofA];
    if (gofB >= 0) rvB = xg[gofB];

    float pi[9], pj[9], acc[9][9];
#pragma unroll
    for (int a = 0; a < 9; a++)
#pragma unroll
        for (int c = 0; c < 9; c++) acc[a][c] = 0.f;

    for (int t = 0; t < T_; t++) {
        const int buf = t & 1;
        float* xb = xs[buf];

        // stage x_t; prefetch x_{t+1} (clamped)
        if (gofA >= 0) xb[sofA] = rvA;
        if (gofB >= 0) xb[sofB] = rvB;
        {
            const int tn = (t + 1 < T_) ? t + 1 : T_ - 1;
            const float* xn = xg + (size_t)tn * NV * HW_;
            if (gofA >= 0) rvA = xn[gofA];
            if (gofB >= 0) rvB = xn[gofB];
        }
        __syncthreads();   // the ONLY bar per t

        // ---- conv: 3 channels of this thread's pixel ----
        float mf0 = bi0, mf1 = bi1, mf2 = bi2;
#pragma unroll
        for (int v = 0; v < 4; v++) {
            float xv[9];
#pragma unroll
            for (int dy = 0; dy < 3; dy++)
#pragma unroll
                for (int dx = 0; dx < 3; dx++)
                    xv[dy * 3 + dx] = xb[xoff + v * 154 + dy * 22 + dx];
#pragma unroll
            for (int c = 0; c < 3; c++) {
                const float4* wp = (const float4*)(ws2 + (k0ch + c) * 48 + v * 12);
                const float4 w0 = wp[0];
                const float4 w1 = wp[1];
                const float w8 = ws2[(k0ch + c) * 48 + v * 12 + 8];
                float s = xv[0] * w0.x;
                s = fmaf(xv[1], w0.y, s);
                s = fmaf(xv[2], w0.z, s);
                s = fmaf(xv[3], w0.w, s);
                s = fmaf(xv[4], w1.x, s);
                s = fmaf(xv[5], w1.y, s);
                s = fmaf(xv[6], w1.z, s);
                s = fmaf(xv[7], w1.w, s);
                s = fmaf(xv[8], w8, s);
                if (c == 0) mf0 += s; else if (c == 1) mf1 += s; else mf2 += s;
            }
        }
        const float mf3 = xb[q * 154 + xoff + 23];           // copy ch 12+q
        const float mf4 = (float)t * (1.0f / 95.0f);         // time ch

        // ---- exchange + immediate consumption (no cur/cj arrays) ----
        const bool t0 = (t == 0);
        float d[9], ci[9];

#define XCH(F, VSRC, SRC)                                                  \
        {                                                                  \
            const float v = __shfl_sync(mask4, (VSRC), base + (SRC), 32);  \
            if ((F) < 9) {                                                 \
                if (!jhi) {                                                \
                    if (t0) pj[(F)] = v;                                   \
                    else { d[(F)] = v - pj[(F)]; pj[(F)] = v; }            \
                }                                                          \
                if (!ihi) ci[(F)] = v;                                     \
            }                                                              \
            if ((F) >= 8) {                                                \
                if (jhi) {                                                 \
                    if (t0) pj[(F) - 8] = v;                               \
                    else { d[(F) - 8] = v - pj[(F) - 8]; pj[(F) - 8] = v; }\
                }                                                          \
                if (ihi) ci[(F) - 8] = v;                                  \
            }                                                              \
        }

        XCH(0,  mf0, 0)  XCH(1,  mf1, 0)  XCH(2,  mf2, 0)
        XCH(3,  mf0, 1)  XCH(4,  mf1, 1)  XCH(5,  mf2, 1)
        XCH(6,  mf0, 2)  XCH(7,  mf1, 2)  XCH(8,  mf2, 2)
        XCH(9,  mf0, 3)  XCH(10, mf1, 3)  XCH(11, mf2, 3)
        XCH(12, mf3, 0)  XCH(13, mf3, 1)  XCH(14, mf3, 2)  XCH(15, mf3, 3)
        XCH(16, mf4, 0)
#undef XCH

        if (t0) {
#pragma unroll
            for (int a = 0; a < 9; a++) pi[a] = ci[a];
            // snapshot p0 to smem (each thread writes its own 5 features)
            p0s[(k0ch + 0) * 100 + pp] = mf0;
            p0s[(k0ch + 1) * 100 + pp] = mf1;
            p0s[(k0ch + 2) * 100 + pp] = mf2;
            p0s[(12 + q) * 100 + pp] = mf3;
            if (q == 0) p0s[16 * 100 + pp] = mf4;
        } else {
#pragma unroll
            for (int a = 0; a < 9; a++) {
                const float m = ci[a] + pi[a];   // 0.5 deferred
                pi[a] = ci[a];
#pragma unroll
                for (int c = 0; c < 9; c++)
                    acc[a][c] = fmaf(m, d[c], acc[a][c]);
            }
        }
    }

    __syncthreads();   // p0s complete

    const int i0 = (q >> 1) * 8, j0 = (q & 1) * 8;
    float p0i[9], l1[9];
#pragma unroll
    for (int a = 0; a < 9; a++) p0i[a] = p0s[(i0 + a) * 100 + pp];
#pragma unroll
    for (int c = 0; c < 9; c++) l1[c] = pj[c] - p0s[(j0 + c) * 100 + pp];

    float* sg = g_sig + ((size_t)b * HW_ + pbase + pp) * SIGLEN_;
    if (q < 2) {
#pragma unroll
        for (int c = 0; c < 9; c++) sg[j0 + c] = l1[c];
    }
#pragma unroll
    for (int a = 0; a < 9; a++)
#pragma unroll
        for (int c = 0; c < 9; c++)
            sg[17 + (i0 + a) * 17 + (j0 + c)] = 0.5f * acc[a][c] - p0i[a] * l1[c];
}

// ---------------------------------------------------------------------------
// Layer-1 GEMM partials over K=122400, 255 chunks of 480. Reg prefetch.
// ---------------------------------------------------------------------------
__global__ __launch_bounds__(256)
void mlp1_kernel(const float* __restrict__ w1)
{
    __shared__ __align__(16) float ss[32 * 66];
    __shared__ __align__(16) float wsm[32 * 32];

    const int cx = blockIdx.x, tid = threadIdx.x;
    const int oq = tid & 7, bq = tid >> 3;
    const int b0 = bq * 2, o0 = oq * 4;
    const int kb = cx * KC_;

    float ps[8], pw[4];
    {
        const int k0 = kb;
#pragma unroll
        for (int r = 0; r < 8; r++) {
            const int idx = tid + r * 256;
            ps[r] = g_sig[(size_t)(idx >> 5) * KTOT_ + k0 + (idx & 31)];
        }
#pragma unroll
        for (int r = 0; r < 4; r++) {
            const int idx = tid + r * 256;
            pw[r] = w1[(size_t)(k0 + (idx >> 5)) * 32 + (idx & 31)];
        }
    }

    float acc[2][4] = {};

    for (int tile = 0; tile < KC_ / 32; tile++) {
#pragma unroll
        for (int r = 0; r < 8; r++) {
            const int idx = tid + r * 256;
            ss[(idx & 31) * 66 + (idx >> 5)] = ps[r];
        }
#pragma unroll
        for (int r = 0; r < 4; r++) {
            const int idx = tid + r * 256;
            wsm[(idx >> 5) * 32 + (idx & 31)] = pw[r];
        }
        if (tile < KC_ / 32 - 1) {
            const int k0 = kb + (tile + 1) * 32;
#pragma unroll
            for (int r = 0; r < 8; r++) {
                const int idx = tid + r * 256;
                ps[r] = g_sig[(size_t)(idx >> 5) * KTOT_ + k0 + (idx & 31)];
            }
#pragma unroll
            for (int r = 0; r < 4; r++) {
                const int idx = tid + r * 256;
                pw[r] = w1[(size_t)(k0 + (idx >> 5)) * 32 + (idx & 31)];
            }
        }
        __syncthreads();
#pragma unroll
        for (int kk = 0; kk < 32; kk++) {
            const float2 sv = *(const float2*)&ss[kk * 66 + b0];
            const float4 wv = *(const float4*)&wsm[kk * 32 + o0];
            acc[0][0] = fmaf(sv.x, wv.x, acc[0][0]);
            acc[0][1] = fmaf(sv.x, wv.y, acc[0][1]);
            acc[0][2] = fmaf(sv.x, wv.z, acc[0][2]);
            acc[0][3] = fmaf(sv.x, wv.w, acc[0][3]);
            acc[1][0] = fmaf(sv.y, wv.x, acc[1][0]);
            acc[1][1] = fmaf(sv.y, wv.y, acc[1][1]);
            acc[1][2] = fmaf(sv.y, wv.z, acc[1][2]);
            acc[1][3] = fmaf(sv.y, wv.w, acc[1][3]);
        }
        __syncthreads();
    }
#pragma unroll
    for (int i = 0; i < 2; i++)
#pragma unroll
        for (int j = 0; j < 4; j++)
            g_part[((size_t)cx * 64 + b0 + i) * 32 + o0 + j] = acc[i][j];
}

// ---------------------------------------------------------------------------
// Reduce partials + bias/relu + layers 2..4.
// ---------------------------------------------------------------------------
__global__ __launch_bounds__(256)
void mlp_tail_kernel(const float* __restrict__ b1,
                     const float* __restrict__ w2, const float* __restrict__ b2,
                     const float* __restrict__ w3, const float* __restrict__ b3,
                     const float* __restrict__ w4, const float* __restrict__ b4,
                     float* __restrict__ out)
{
    __shared__ float red[8][33];
    const int b = blockIdx.x, tid = threadIdx.x;
    const int o = tid & 31, g = tid >> 5;

    float s = 0.f;
    for (int c = g; c < NCHUNK_; c += 8)
        s += g_part[((size_t)c * 64 + b) * 32 + o];
    red[g][o] = s;
    __syncthreads();

    if (tid < 32) {
        float s1 = b1[o];
#pragma unroll
        for (int gg = 0; gg < 8; gg++) s1 += red[gg][o];
        float h = fmaxf(s1, 0.f);

        float s2 = b2[o];
#pragma unroll
        for (int k = 0; k < 32; k++)
            s2 = fmaf(__shfl_sync(0xffffffffu, h, k), w2[k * 32 + o], s2);
        h = fmaxf(s2, 0.f);

        float s3 = b3[o];
#pragma unroll
        for (int k = 0; k < 32; k++)
            s3 = fmaf(__shfl_sync(0xffffffffu, h, k), w3[k * 32 + o], s3);
        h = fmaxf(s3, 0.f);

        float v = h * w4[o];
#pragma unroll
        for (int off = 16; off; off >>= 1) v += __shfl_xor_sync(0xffffffffu, v, off);
        if (o == 0) out[b] = v + b4[0];
    }
}

// ---------------------------------------------------------------------------
extern "C" void kernel_launch(void* const* d_in, const int* in_sizes, int n_in,
                              void* d_out, int out_size)
{
    const float* x  = (const float*)d_in[0];
    const float* cw = (const float*)d_in[1];
    const float* cb = (const float*)d_in[2];
    const float* w1 = (const float*)d_in[3];
    const float* b1 = (const float*)d_in[4];
    const float* w2 = (const float*)d_in[5];
    const float* b2 = (const float*)d_in[6];
    const float* w3 = (const float*)d_in[7];
    const float* b3 = (const float*)d_in[8];
    const float* w4 = (const float*)d_in[9];
    const float* b4 = (const float*)d_in[10];
    float* out = (float*)d_out;

    fused_conv_sig_kernel<<<dim3(4, B_), 400>>>(x, cw, cb);
    mlp1_kernel<<<NCHUNK_, 256>>>(w1);
    mlp_tail_kernel<<<B_, 256>>>(b1, w2, b2, w3, b3, w4, b4, out);
}

// round 8
// speedup vs baseline: 1.9401x; 1.9401x over previous
#include <cuda_runtime.h>
#include <cstdint>

#define B_ 64
#define T_ 96
#define NV 4
#define NF_ 17
#define HW_ 400
#define SIGLEN_ 306
#define KTOT_ 122400        // HW_*SIGLEN_
#define NCHUNK_ 255
#define KC_ 480             // NCHUNK_*KC_ == KTOT_

__device__ float g_sig [(size_t)B_ * HW_ * SIGLEN_];    // [b][p][s]  ~31 MB
__device__ float g_part[(size_t)NCHUNK_ * 64 * 32];

// ---------------------------------------------------------------------------
// Fused conv3x3(4->12) + feature assembly + path signature. r4 structure
// (scalar FMA, smem feat tile, 128 regs no-spill) with ONE barrier per t:
// xs double-buffered alongside feat, so per iteration:
//   stage xs[buf^1] = x_{t+1};  conv: xs[buf] -> feat[buf];  BAR;  sig(feat[buf])
// Ordering: conv(k) reads xs[buf] staged at k-1 (across bar_{k-1});
// stage(k) overwrites xs[buf^1] last read by conv(k-1) before bar_{k-1};
// sig(k) reads feat[buf] written by conv(k) across bar_k;
// conv(k+1) overwrites feat[buf^1] last read by sig(k-1) before bar_k.
//   lvl1_j  = p95_j - p0_j
//   lvl2_ij = 0.5*sum_t (p_t+p_{t-1})_i (p_t-p_{t-1})_j - p0_i*lvl1_j
// ---------------------------------------------------------------------------
__global__ __launch_bounds__(400, 1)
void fused_conv_sig_kernel(const float* __restrict__ x,
                           const float* __restrict__ cw,
                           const float* __restrict__ cb)
{
    __shared__ __align__(16) float xs[2][616];         // double-buffered halo (4v x 7 x 22)
    __shared__ __align__(16) float ws2[12 * 48];       // weights [k][v][12pad]
    __shared__ float wb[12];
    __shared__ __align__(16) float feat[2][17 * 101];  // double-buffered feature tile
    __shared__ float p0s[17 * 101];                    // t=0 snapshot

    const int cx = blockIdx.x;
    const int b  = blockIdx.y;
    const int tid = threadIdx.x;
    const int pbase = cx * 100;

    // init: zero both xs buffers (halo guards stay 0), repack weights
    for (int i = tid; i < 2 * 616; i += 400) (&xs[0][0])[i] = 0.f;
    for (int i = tid; i < 432; i += 400) {
        const int k = i / 36, r = i % 36, v = r / 9, tap = r % 9;
        ws2[k * 48 + v * 12 + tap] = cw[i];
    }
    if (tid < 12) wb[tid] = cb[tid];

    // hoisted x-staging indices (2 legs)
    const float* xg = x + (size_t)b * T_ * NV * HW_;
    int gofA = -1, sofA = 0, gofB = -1, sofB = 0;
    {
        const int i = tid;
        const int v = i / 154, r = i % 154, row = r / 22, col = r % 22;
        const int gr = cx * 5 - 1 + row;
        if (gr >= 0 && gr < 20 && col >= 1 && col <= 20) {
            gofA = v * HW_ + gr * 20 + (col - 1); sofA = i;
        }
    }
    if (tid + 400 < 616) {
        const int i = tid + 400;
        const int v = i / 154, r = i % 154, row = r / 22, col = r % 22;
        const int gr = cx * 5 - 1 + row;
        if (gr >= 0 && gr < 20 && col >= 1 && col <= 20) {
            gofB = v * HW_ + gr * 20 + (col - 1); sofB = i;
        }
    }

    // conv role: pixel px, channel group kq (3 channels)
    const int px = tid % 100, kq = tid / 100;
    const int row0 = px / 20, col0 = px % 20;
    const int xoff = row0 * 22 + col0;

    // sig role: pixel pp, quadrant q
    const int pp = tid >> 2, q = tid & 3;
    const int i0 = (q >> 1) * 8, j0 = (q & 1) * 8;

    // stage x_0 into xs[0], prefetch x_1
    float rvA = 0.f, rvB = 0.f;
    if (gofA >= 0) rvA = xg[gofA];
    if (gofB >= 0) rvB = xg[gofB];
    if (gofA >= 0) xs[0][sofA] = rvA;
    if (gofB >= 0) xs[0][sofB] = rvB;
    {
        const float* xn = xg + (size_t)NV * HW_;
        if (gofA >= 0) rvA = xn[gofA];
        if (gofB >= 0) rvB = xn[gofB];
    }
    __syncthreads();   // ws2/wb + xs[0] ready

    const float bi0 = wb[kq * 3], bi1 = wb[kq * 3 + 1], bi2 = wb[kq * 3 + 2];

#define CONV_STEP(XB, FT, TVAL)                                            \
    {                                                                      \
        const float* xrow = (XB) + xoff;                                   \
        float a0 = bi0, a1 = bi1, a2 = bi2;                                \
        _Pragma("unroll")                                                  \
        for (int v = 0; v < 4; v++) {                                      \
            float xv[9];                                                   \
            _Pragma("unroll")                                              \
            for (int dy = 0; dy < 3; dy++)                                 \
                _Pragma("unroll")                                          \
                for (int dx = 0; dx < 3; dx++)                             \
                    xv[dy * 3 + dx] = xrow[v * 154 + dy * 22 + dx];        \
            _Pragma("unroll")                                              \
            for (int c = 0; c < 3; c++) {                                  \
                const float4* wp = (const float4*)(ws2 + (kq * 3 + c) * 48 + v * 12); \
                const float4 w0 = wp[0];                                   \
                const float4 w1 = wp[1];                                   \
                const float w8 = ws2[(kq * 3 + c) * 48 + v * 12 + 8];      \
                float s = xv[0] * w0.x;                                    \
                s = fmaf(xv[1], w0.y, s);                                  \
                s = fmaf(xv[2], w0.z, s);                                  \
                s = fmaf(xv[3], w0.w, s);                                  \
                s = fmaf(xv[4], w1.x, s);                                  \
                s = fmaf(xv[5], w1.y, s);                                  \
                s = fmaf(xv[6], w1.z, s);                                  \
                s = fmaf(xv[7], w1.w, s);                                  \
                s = fmaf(xv[8], w8, s);                                    \
                if (c == 0) a0 += s; else if (c == 1) a1 += s; else a2 += s; \
            }                                                              \
        }                                                                  \
        (FT)[(kq * 3 + 0) * 101 + px] = a0;                                \
        (FT)[(kq * 3 + 1) * 101 + px] = a1;                                \
        (FT)[(kq * 3 + 2) * 101 + px] = a2;                                \
        (FT)[(12 + kq) * 101 + px] = xrow[kq * 154 + 23];                  \
        if (kq == 0) (FT)[16 * 101 + px] = (TVAL);                         \
    }

    // prologue: conv(0) -> feat[0]; stage xs[1]=x1; prefetch x2
    CONV_STEP(xs[0], feat[0], 0.f)
    if (gofA >= 0) xs[1][sofA] = rvA;
    if (gofB >= 0) xs[1][sofB] = rvB;
    {
        const float* xn = xg + (size_t)2 * NV * HW_;
        if (gofA >= 0) rvA = xn[gofA];
        if (gofB >= 0) rvB = xn[gofB];
    }
    __syncthreads();   // feat[0] + xs[1] ready

    // sig init from feat[0]
    float pi[9], pj[9], acc[9][9];
#pragma unroll
    for (int a = 0; a < 9; a++) pi[a] = feat[0][(i0 + a) * 101 + pp];
#pragma unroll
    for (int c = 0; c < 9; c++) pj[c] = feat[0][(j0 + c) * 101 + pp];
#pragma unroll
    for (int a = 0; a < 9; a++)
#pragma unroll
        for (int c = 0; c < 9; c++) acc[a][c] = 0.f;
    for (int i = tid; i < 17 * 101; i += 400) p0s[i] = feat[0][i];

    for (int k = 1; k < T_; k++) {
        const int buf = k & 1;
        float* ft = feat[buf];
        const float* xb = xs[buf];

        // stage x_{k+1} into other xs buffer; prefetch x_{k+2} (clamped)
        if (gofA >= 0) xs[buf ^ 1][sofA] = rvA;
        if (gofB >= 0) xs[buf ^ 1][sofB] = rvB;
        {
            const int tn = (k + 2 < T_) ? (k + 2) : (T_ - 1);
            const float* xn = xg + (size_t)tn * NV * HW_;
            if (gofA >= 0) rvA = xn[gofA];
            if (gofB >= 0) rvB = xn[gofB];
        }

        // conv(k): xs[buf] (staged at k-1, bar-protected) -> feat[buf]
        CONV_STEP(xb, ft, (float)k * (1.0f / 95.0f))

        __syncthreads();   // the ONLY bar per t

        // sig(k): scalar rank-1 update
        float d[9];
#pragma unroll
        for (int c = 0; c < 9; c++) {
            const float cv = ft[(j0 + c) * 101 + pp];
            d[c] = cv - pj[c];
            pj[c] = cv;
        }
#pragma unroll
        for (int a = 0; a < 9; a++) {
            const float cv = ft[(i0 + a) * 101 + pp];
            const float m = cv + pi[a];      // 0.5 deferred
            pi[a] = cv;
#pragma unroll
            for (int c = 0; c < 9; c++)
                acc[a][c] = fmaf(m, d[c], acc[a][c]);
        }
    }
#undef CONV_STEP

    // epilogue
    float p0i[9], l1[9];
#pragma unroll
    for (int a = 0; a < 9; a++) p0i[a] = p0s[(i0 + a) * 101 + pp];
#pragma unroll
    for (int c = 0; c < 9; c++) l1[c] = pj[c] - p0s[(j0 + c) * 101 + pp];

    float* sg = g_sig + ((size_t)b * HW_ + pbase + pp) * SIGLEN_;
    if (q < 2) {
#pragma unroll
        for (int c = 0; c < 9; c++) sg[j0 + c] = l1[c];
    }
#pragma unroll
    for (int a = 0; a < 9; a++)
#pragma unroll
        for (int c = 0; c < 9; c++)
            sg[17 + (i0 + a) * 17 + (j0 + c)] = 0.5f * acc[a][c] - p0i[a] * l1[c];
}

// ---------------------------------------------------------------------------
// Layer-1 GEMM partials over K=122400, 255 chunks of 480. Reg prefetch.
// ---------------------------------------------------------------------------
__global__ __launch_bounds__(256)
void mlp1_kernel(const float* __restrict__ w1)
{
    __shared__ __align__(16) float ss[32 * 66];
    __shared__ __align__(16) float wsm[32 * 32];

    const int cx = blockIdx.x, tid = threadIdx.x;
    const int oq = tid & 7, bq = tid >> 3;
    const int b0 = bq * 2, o0 = oq * 4;
    const int kb = cx * KC_;

    float ps[8], pw[4];
    {
        const int k0 = kb;
#pragma unroll
        for (int r = 0; r < 8; r++) {
            const int idx = tid + r * 256;
            ps[r] = g_sig[(size_t)(idx >> 5) * KTOT_ + k0 + (idx & 31)];
        }
#pragma unroll
        for (int r = 0; r < 4; r++) {
            const int idx = tid + r * 256;
            pw[r] = w1[(size_t)(k0 + (idx >> 5)) * 32 + (idx & 31)];
        }
    }

    float acc[2][4] = {};

    for (int tile = 0; tile < KC_ / 32; tile++) {
#pragma unroll
        for (int r = 0; r < 8; r++) {
            const int idx = tid + r * 256;
            ss[(idx & 31) * 66 + (idx >> 5)] = ps[r];
        }
#pragma unroll
        for (int r = 0; r < 4; r++) {
            const int idx = tid + r * 256;
            wsm[(idx >> 5) * 32 + (idx & 31)] = pw[r];
        }
        if (tile < KC_ / 32 - 1) {
            const int k0 = kb + (tile + 1) * 32;
#pragma unroll
            for (int r = 0; r < 8; r++) {
                const int idx = tid + r * 256;
                ps[r] = g_sig[(size_t)(idx >> 5) * KTOT_ + k0 + (idx & 31)];
            }
#pragma unroll
            for (int r = 0; r < 4; r++) {
                const int idx = tid + r * 256;
                pw[r] = w1[(size_t)(k0 + (idx >> 5)) * 32 + (idx & 31)];
            }
        }
        __syncthreads();
#pragma unroll
        for (int kk = 0; kk < 32; kk++) {
            const float2 sv = *(const float2*)&ss[kk * 66 + b0];
            const float4 wv = *(const float4*)&wsm[kk * 32 + o0];
            acc[0][0] = fmaf(sv.x, wv.x, acc[0][0]);
            acc[0][1] = fmaf(sv.x, wv.y, acc[0][1]);
            acc[0][2] = fmaf(sv.x, wv.z, acc[0][2]);
            acc[0][3] = fmaf(sv.x, wv.w, acc[0][3]);
            acc[1][0] = fmaf(sv.y, wv.x, acc[1][0]);
            acc[1][1] = fmaf(sv.y, wv.y, acc[1][1]);
            acc[1][2] = fmaf(sv.y, wv.z, acc[1][2]);
            acc[1][3] = fmaf(sv.y, wv.w, acc[1][3]);
        }
        __syncthreads();
    }
#pragma unroll
    for (int i = 0; i < 2; i++)
#pragma unroll
        for (int j = 0; j < 4; j++)
            g_part[((size_t)cx * 64 + b0 + i) * 32 + o0 + j] = acc[i][j];
}

// ---------------------------------------------------------------------------
// Reduce partials + bias/relu + layers 2..4.
// ---------------------------------------------------------------------------
__global__ __launch_bounds__(256)
void mlp_tail_kernel(const float* __restrict__ b1,
                     const float* __restrict__ w2, const float* __restrict__ b2,
                     const float* __restrict__ w3, const float* __restrict__ b3,
                     const float* __restrict__ w4, const float* __restrict__ b4,
                     float* __restrict__ out)
{
    __shared__ float red[8][33];
    const int b = blockIdx.x, tid = threadIdx.x;
    const int o = tid & 31, g = tid >> 5;

    float s = 0.f;
    for (int c = g; c < NCHUNK_; c += 8)
        s += g_part[((size_t)c * 64 + b) * 32 + o];
    red[g][o] = s;
    __syncthreads();

    if (tid < 32) {
        float s1 = b1[o];
#pragma unroll
        for (int gg = 0; gg < 8; gg++) s1 += red[gg][o];
        float h = fmaxf(s1, 0.f);

        float s2 = b2[o];
#pragma unroll
        for (int k = 0; k < 32; k++)
            s2 = fmaf(__shfl_sync(0xffffffffu, h, k), w2[k * 32 + o], s2);
        h = fmaxf(s2, 0.f);

        float s3 = b3[o];
#pragma unroll
        for (int k = 0; k < 32; k++)
            s3 = fmaf(__shfl_sync(0xffffffffu, h, k), w3[k * 32 + o], s3);
        h = fmaxf(s3, 0.f);

        float v = h * w4[o];
#pragma unroll
        for (int off = 16; off; off >>= 1) v += __shfl_xor_sync(0xffffffffu, v, off);
        if (o == 0) out[b] = v + b4[0];
    }
}

// ---------------------------------------------------------------------------
extern "C" void kernel_launch(void* const* d_in, const int* in_sizes, int n_in,
                              void* d_out, int out_size)
{
    const float* x  = (const float*)d_in[0];
    const float* cw = (const float*)d_in[1];
    const float* cb = (const float*)d_in[2];
    const float* w1 = (const float*)d_in[3];
    const float* b1 = (const float*)d_in[4];
    const float* w2 = (const float*)d_in[5];
    const float* b2 = (const float*)d_in[6];
    const float* w3 = (const float*)d_in[7];
    const float* b3 = (const float*)d_in[8];
    const float* w4 = (const float*)d_in[9];
    const float* b4 = (const float*)d_in[10];
    float* out = (float*)d_out;

    fused_conv_sig_kernel<<<dim3(4, B_), 400>>>(x, cw, cb);
    mlp1_kernel<<<NCHUNK_, 256>>>(w1);
    mlp_tail_kernel<<<B_, 256>>>(b1, w2, b2, w3, b3, w4, b4, out);
}

// round 9
// speedup vs baseline: 2.0005x; 1.0311x over previous
#include <cuda_runtime.h>
#include <cstdint>

#define B_ 64
#define T_ 96
#define NV 4
#define NF_ 17
#define HW_ 400
#define SIGLEN_ 306
#define KTOT_ 122400        // HW_*SIGLEN_
#define NCHUNK_ 255
#define KC_ 480             // NCHUNK_*KC_ == KTOT_

#define PX_ 40              // pixels per block (2 rows of 20)
#define THR_ 160            // threads per block
#define NSTRIP_ 10          // strips per image
#define XSZ_ 352            // halo floats: 4 rows x 22 cols x 4 vars

__device__ float g_sig [(size_t)B_ * HW_ * SIGLEN_];    // [b][p][s]  ~31 MB
__device__ float g_part[(size_t)NCHUNK_ * 64 * 32];

// ---------------------------------------------------------------------------
// Fused conv3x3(4->12) + feature assembly + path signature.
// r8 inner math verbatim; decomposition changed to 2-row strips:
// grid (10, 64), 160 threads, occupancy 3 (15 warps/SM, reg cap 136).
// One __syncthreads per t:
//   stage xs[buf^1]=x_{t+1};  conv: xs[buf]->feat[buf];  BAR;  sig(feat[buf])
//   lvl1_j  = p95_j - p0_j
//   lvl2_ij = 0.5*sum_t (p_t+p_{t-1})_i (p_t-p_{t-1})_j - p0_i*lvl1_j
// ---------------------------------------------------------------------------
__global__ __launch_bounds__(THR_, 3)
void fused_conv_sig_kernel(const float* __restrict__ x,
                           const float* __restrict__ cw,
                           const float* __restrict__ cb)
{
    __shared__ __align__(16) float xs[2][XSZ_];        // halo: 4v x 4rows x 22
    __shared__ __align__(16) float ws2[12 * 48];       // weights [k][v][12pad]
    __shared__ float wb[12];
    __shared__ __align__(16) float feat[2][17 * 41];   // double-buffered feature tile
    __shared__ float p0s[17 * 41];                     // t=0 snapshot

    const int cx = blockIdx.x;          // 2-row strip: rows 2cx..2cx+1
    const int b  = blockIdx.y;
    const int tid = threadIdx.x;
    const int pbase = cx * PX_;

    // init: zero both xs buffers (halo guards stay 0), repack weights
    for (int i = tid; i < 2 * XSZ_; i += THR_) (&xs[0][0])[i] = 0.f;
    for (int i = tid; i < 432; i += THR_) {
        const int k = i / 36, r = i % 36, v = r / 9, tap = r % 9;
        ws2[k * 48 + v * 12 + tap] = cw[i];
    }
    if (tid < 12) wb[tid] = cb[tid];

    // hoisted x-staging indices (3 legs: tid, tid+160, tid+320)
    const float* xg = x + (size_t)b * T_ * NV * HW_;
    int gof[3], sof[3];
#pragma unroll
    for (int l = 0; l < 3; l++) {
        const int i = tid + l * THR_;
        gof[l] = -1; sof[l] = 0;
        if (i < XSZ_) {
            const int v = i / 88, r = i % 88, row = r / 22, col = r % 22;
            const int gr = cx * 2 - 1 + row;
            if (gr >= 0 && gr < 20 && col >= 1 && col <= 20) {
                gof[l] = v * HW_ + gr * 20 + (col - 1); sof[l] = i;
            }
        }
    }

    // conv role: pixel px, channel group kq (3 channels)
    const int px = tid % PX_, kq = tid / PX_;
    const int row0 = px / 20, col0 = px % 20;
    const int xoff = row0 * 22 + col0;

    // sig role: pixel pp, quadrant q
    const int pp = tid >> 2, q = tid & 3;
    const int i0 = (q >> 1) * 8, j0 = (q & 1) * 8;

    // stage x_0 into xs[0], prefetch x_1
    float rv[3] = {0.f, 0.f, 0.f};
#pragma unroll
    for (int l = 0; l < 3; l++) if (gof[l] >= 0) rv[l] = xg[gof[l]];
#pragma unroll
    for (int l = 0; l < 3; l++) if (gof[l] >= 0) xs[0][sof[l]] = rv[l];
    {
        const float* xn = xg + (size_t)NV * HW_;
#pragma unroll
        for (int l = 0; l < 3; l++) if (gof[l] >= 0) rv[l] = xn[gof[l]];
    }
    __syncthreads();   // ws2/wb + xs[0] ready

    const float bi0 = wb[kq * 3], bi1 = wb[kq * 3 + 1], bi2 = wb[kq * 3 + 2];

#define CONV_STEP(XB, FT, TVAL)                                            \
    {                                                                      \
        const float* xrow = (XB) + xoff;                                   \
        float a0 = bi0, a1 = bi1, a2 = bi2;                                \
        _Pragma("unroll")                                                  \
        for (int v = 0; v < 4; v++) {                                      \
            float xv[9];                                                   \
            _Pragma("unroll")                                              \
            for (int dy = 0; dy < 3; dy++)                                 \
                _Pragma("unroll")                                          \
                for (int dx = 0; dx < 3; dx++)                             \
                    xv[dy * 3 + dx] = xrow[v * 88 + dy * 22 + dx];         \
            _Pragma("unroll")                                              \
            for (int c = 0; c < 3; c++) {                                  \
                const float4* wp = (const float4*)(ws2 + (kq * 3 + c) * 48 + v * 12); \
                const float4 w0 = wp[0];                                   \
                const float4 w1 = wp[1];                                   \
                const float w8 = ws2[(kq * 3 + c) * 48 + v * 12 + 8];      \
                float s = xv[0] * w0.x;                                    \
                s = fmaf(xv[1], w0.y, s);                                  \
                s = fmaf(xv[2], w0.z, s);                                  \
                s = fmaf(xv[3], w0.w, s);                                  \
                s = fmaf(xv[4], w1.x, s);                                  \
                s = fmaf(xv[5], w1.y, s);                                  \
                s = fmaf(xv[6], w1.z, s);                                  \
                s = fmaf(xv[7], w1.w, s);                                  \
                s = fmaf(xv[8], w8, s);                                    \
                if (c == 0) a0 += s; else if (c == 1) a1 += s; else a2 += s; \
            }                                                              \
        }                                                                  \
        (FT)[(kq * 3 + 0) * 41 + px] = a0;                                 \
        (FT)[(kq * 3 + 1) * 41 + px] = a1;                                 \
        (FT)[(kq * 3 + 2) * 41 + px] = a2;                                 \
        (FT)[(12 + kq) * 41 + px] = xrow[kq * 88 + 23];                    \
        if (kq == 0) (FT)[16 * 41 + px] = (TVAL);                          \
    }

    // prologue: conv(0) -> feat[0]; stage xs[1]=x1; prefetch x2
    CONV_STEP(xs[0], feat[0], 0.f)
#pragma unroll
    for (int l = 0; l < 3; l++) if (gof[l] >= 0) xs[1][sof[l]] = rv[l];
    {
        const float* xn = xg + (size_t)2 * NV * HW_;
#pragma unroll
        for (int l = 0; l < 3; l++) if (gof[l] >= 0) rv[l] = xn[gof[l]];
    }
    __syncthreads();   // feat[0] + xs[1] ready

    // sig init from feat[0]
    float pi[9], pj[9], acc[9][9];
#pragma unroll
    for (int a = 0; a < 9; a++) pi[a] = feat[0][(i0 + a) * 41 + pp];
#pragma unroll
    for (int c = 0; c < 9; c++) pj[c] = feat[0][(j0 + c) * 41 + pp];
#pragma unroll
    for (int a = 0; a < 9; a++)
#pragma unroll
        for (int c = 0; c < 9; c++) acc[a][c] = 0.f;
    for (int i = tid; i < 17 * 41; i += THR_) p0s[i] = feat[0][i];

    for (int k = 1; k < T_; k++) {
        const int buf = k & 1;
        float* ft = feat[buf];
        const float* xb = xs[buf];

        // stage x_{k+1} into other xs buffer; prefetch x_{k+2} (clamped)
#pragma unroll
        for (int l = 0; l < 3; l++) if (gof[l] >= 0) xs[buf ^ 1][sof[l]] = rv[l];
        {
            const int tn = (k + 2 < T_) ? (k + 2) : (T_ - 1);
            const float* xn = xg + (size_t)tn * NV * HW_;
#pragma unroll
            for (int l = 0; l < 3; l++) if (gof[l] >= 0) rv[l] = xn[gof[l]];
        }

        // conv(k): xs[buf] (staged at k-1, bar-protected) -> feat[buf]
        CONV_STEP(xb, ft, (float)k * (1.0f / 95.0f))

        __syncthreads();   // the ONLY bar per t

        // sig(k): scalar rank-1 update
        float d[9];
#pragma unroll
        for (int c = 0; c < 9; c++) {
            const float cv = ft[(j0 + c) * 41 + pp];
            d[c] = cv - pj[c];
            pj[c] = cv;
        }
#pragma unroll
        for (int a = 0; a < 9; a++) {
            const float cv = ft[(i0 + a) * 41 + pp];
            const float m = cv + pi[a];      // 0.5 deferred
            pi[a] = cv;
#pragma unroll
            for (int c = 0; c < 9; c++)
                acc[a][c] = fmaf(m, d[c], acc[a][c]);
        }
    }
#undef CONV_STEP

    // epilogue
    float p0i[9], l1[9];
#pragma unroll
    for (int a = 0; a < 9; a++) p0i[a] = p0s[(i0 + a) * 41 + pp];
#pragma unroll
    for (int c = 0; c < 9; c++) l1[c] = pj[c] - p0s[(j0 + c) * 41 + pp];

    float* sg = g_sig + ((size_t)b * HW_ + pbase + pp) * SIGLEN_;
    if (q < 2) {
#pragma unroll
        for (int c = 0; c < 9; c++) sg[j0 + c] = l1[c];
    }
#pragma unroll
    for (int a = 0; a < 9; a++)
#pragma unroll
        for (int c = 0; c < 9; c++)
            sg[17 + (i0 + a) * 17 + (j0 + c)] = 0.5f * acc[a][c] - p0i[a] * l1[c];
}

// ---------------------------------------------------------------------------
// Layer-1 GEMM partials over K=122400, 255 chunks of 480. Reg prefetch.
// ---------------------------------------------------------------------------
__global__ __launch_bounds__(256)
void mlp1_kernel(const float* __restrict__ w1)
{
    __shared__ __align__(16) float ss[32 * 66];
    __shared__ __align__(16) float wsm[32 * 32];

    const int cx = blockIdx.x, tid = threadIdx.x;
    const int oq = tid & 7, bq = tid >> 3;
    const int b0 = bq * 2, o0 = oq * 4;
    const int kb = cx * KC_;

    float ps[8], pw[4];
    {
        const int k0 = kb;
#pragma unroll
        for (int r = 0; r < 8; r++) {
            const int idx = tid + r * 256;
            ps[r] = g_sig[(size_t)(idx >> 5) * KTOT_ + k0 + (idx & 31)];
        }
#pragma unroll
        for (int r = 0; r < 4; r++) {
            const int idx = tid + r * 256;
            pw[r] = w1[(size_t)(k0 + (idx >> 5)) * 32 + (idx & 31)];
        }
    }

    float acc[2][4] = {};

    for (int tile = 0; tile < KC_ / 32; tile++) {
#pragma unroll
        for (int r = 0; r < 8; r++) {
            const int idx = tid + r * 256;
            ss[(idx & 31) * 66 + (idx >> 5)] = ps[r];
        }
#pragma unroll
        for (int r = 0; r < 4; r++) {
            const int idx = tid + r * 256;
            wsm[(idx >> 5) * 32 + (idx & 31)] = pw[r];
        }
        if (tile < KC_ / 32 - 1) {
            const int k0 = kb + (tile + 1) * 32;
#pragma unroll
            for (int r = 0; r < 8; r++) {
                const int idx = tid + r * 256;
                ps[r] = g_sig[(size_t)(idx >> 5) * KTOT_ + k0 + (idx & 31)];
            }
#pragma unroll
            for (int r = 0; r < 4; r++) {
                const int idx = tid + r * 256;
                pw[r] = w1[(size_t)(k0 + (idx >> 5)) * 32 + (idx & 31)];
            }
        }
        __syncthreads();
#pragma unroll
        for (int kk = 0; kk < 32; kk++) {
            const float2 sv = *(const float2*)&ss[kk * 66 + b0];
            const float4 wv = *(const float4*)&wsm[kk * 32 + o0];
            acc[0][0] = fmaf(sv.x, wv.x, acc[0][0]);
            acc[0][1] = fmaf(sv.x, wv.y, acc[0][1]);
            acc[0][2] = fmaf(sv.x, wv.z, acc[0][2]);
            acc[0][3] = fmaf(sv.x, wv.w, acc[0][3]);
            acc[1][0] = fmaf(sv.y, wv.x, acc[1][0]);
            acc[1][1] = fmaf(sv.y, wv.y, acc[1][1]);
            acc[1][2] = fmaf(sv.y, wv.z, acc[1][2]);
            acc[1][3] = fmaf(sv.y, wv.w, acc[1][3]);
        }
        __syncthreads();
    }
#pragma unroll
    for (int i = 0; i < 2; i++)
#pragma unroll
        for (int j = 0; j < 4; j++)
            g_part[((size_t)cx * 64 + b0 + i) * 32 + o0 + j] = acc[i][j];
}

// ---------------------------------------------------------------------------
// Reduce partials + bias/relu + layers 2..4.
// ---------------------------------------------------------------------------
__global__ __launch_bounds__(256)
void mlp_tail_kernel(const float* __restrict__ b1,
                     const float* __restrict__ w2, const float* __restrict__ b2,
                     const float* __restrict__ w3, const float* __restrict__ b3,
                     const float* __restrict__ w4, const float* __restrict__ b4,
                     float* __restrict__ out)
{
    __shared__ float red[8][33];
    const int b = blockIdx.x, tid = threadIdx.x;
    const int o = tid & 31, g = tid >> 5;

    float s = 0.f;
    for (int c = g; c < NCHUNK_; c += 8)
        s += g_part[((size_t)c * 64 + b) * 32 + o];
    red[g][o] = s;
    __syncthreads();

    if (tid < 32) {
        float s1 = b1[o];
#pragma unroll
        for (int gg = 0; gg < 8; gg++) s1 += red[gg][o];
        float h = fmaxf(s1, 0.f);

        float s2 = b2[o];
#pragma unroll
        for (int k = 0; k < 32; k++)
            s2 = fmaf(__shfl_sync(0xffffffffu, h, k), w2[k * 32 + o], s2);
        h = fmaxf(s2, 0.f);

        float s3 = b3[o];
#pragma unroll
        for (int k = 0; k < 32; k++)
            s3 = fmaf(__shfl_sync(0xffffffffu, h, k), w3[k * 32 + o], s3);
        h = fmaxf(s3, 0.f);

        float v = h * w4[o];
#pragma unroll
        for (int off = 16; off; off >>= 1) v += __shfl_xor_sync(0xffffffffu, v, off);
        if (o == 0) out[b] = v + b4[0];
    }
}

// ---------------------------------------------------------------------------
extern "C" void kernel_launch(void* const* d_in, const int* in_sizes, int n_in,
                              void* d_out, int out_size)
{
    const float* x  = (const float*)d_in[0];
    const float* cw = (const float*)d_in[1];
    const float* cb = (const float*)d_in[2];
    const float* w1 = (const float*)d_in[3];
    const float* b1 = (const float*)d_in[4];
    const float* w2 = (const float*)d_in[5];
    const float* b2 = (const float*)d_in[6];
    const float* w3 = (const float*)d_in[7];
    const float* b3 = (const float*)d_in[8];
    const float* w4 = (const float*)d_in[9];
    const float* b4 = (const float*)d_in[10];
    float* out = (float*)d_out;

    fused_conv_sig_kernel<<<dim3(NSTRIP_, B_), THR_>>>(x, cw, cb);
    mlp1_kernel<<<NCHUNK_, 256>>>(w1);
    mlp_tail_kernel<<<B_, 256>>>(b1, w2, b2, w3, b3, w4, b4, out);
}

// round 10
// speedup vs baseline: 2.1746x; 1.0870x over previous
#include <cuda_runtime.h>
#include <cstdint>

#define B_ 64
#define T_ 96
#define NV 4
#define NF_ 17
#define HW_ 400
#define SIGLEN_ 306
#define KTOT_ 122400        // HW_*SIGLEN_
#define NCHUNK_ 255
#define KC_ 480             // NCHUNK_*KC_ == KTOT_

#define PX_ 40              // pixels per block (2 rows of 20)
#define THR_ 160            // threads per block
#define NSTRIP_ 10          // strips per image
#define XSZ_ 352            // halo floats: 4 vars x 4 rows x 22 cols

__device__ float g_sig [(size_t)B_ * HW_ * SIGLEN_];    // [b][p][s]  ~31 MB
__device__ float g_part[(size_t)NCHUNK_ * 64 * 32];

// ---------------------------------------------------------------------------
// Fused conv3x3(4->12) + feature assembly + path signature.
// 160 threads, occ 3, ONE __syncthreads per t. Feature tile TRIPLE-buffered;
// the signature update reads both current (k%3) and previous ((k-1)%3)
// buffers, so NO pi/pj register state exists -> live regs ~120, no spills.
// Race check (1 bar per iter): sig(k) [post bar_k] reads feat[k%3] and
// feat[(k-1)%3]; conv(k+1) [post bar_k] writes feat[(k+1)%3] - disjoint.
// feat[(k+1)%3]'s previous readers (sig(k-1), pre bar_k) are done. xs double
// buffer as in r8/r9.
//   lvl1_j  = p95_j - p0_j
//   lvl2_ij = 0.5*sum_t (p_t+p_{t-1})_i (p_t-p_{t-1})_j - p0_i*lvl1_j
// ---------------------------------------------------------------------------
__global__ __launch_bounds__(THR_, 3)
void fused_conv_sig_kernel(const float* __restrict__ x,
                           const float* __restrict__ cw,
                           const float* __restrict__ cb)
{
    __shared__ __align__(16) float xs[2][XSZ_];        // halo: 4v x 4rows x 22
    __shared__ __align__(16) float ws2[12 * 48];       // weights [k][v][12pad]
    __shared__ float wb[12];
    __shared__ __align__(16) float feat[3][17 * 41];   // TRIPLE-buffered feature tile
    __shared__ float p0s[17 * 41];                     // t=0 snapshot

    const int cx = blockIdx.x;          // 2-row strip: rows 2cx..2cx+1
    const int b  = blockIdx.y;
    const int tid = threadIdx.x;
    const int pbase = cx * PX_;

    // init: zero both xs buffers (halo guards stay 0), repack weights
    for (int i = tid; i < 2 * XSZ_; i += THR_) (&xs[0][0])[i] = 0.f;
    for (int i = tid; i < 432; i += THR_) {
        const int k = i / 36, r = i % 36, v = r / 9, tap = r % 9;
        ws2[k * 48 + v * 12 + tap] = cw[i];
    }
    if (tid < 12) wb[tid] = cb[tid];

    // hoisted x-staging offsets (3 legs; smem offset = tid + l*THR_, no array)
    const float* xg = x + (size_t)b * T_ * NV * HW_;
    int gof[3];
#pragma unroll
    for (int l = 0; l < 3; l++) {
        const int i = tid + l * THR_;
        gof[l] = -1;
        if (i < XSZ_) {
            const int v = i / 88, r = i % 88, row = r / 22, col = r % 22;
            const int gr = cx * 2 - 1 + row;
            if (gr >= 0 && gr < 20 && col >= 1 && col <= 20)
                gof[l] = v * HW_ + gr * 20 + (col - 1);
        }
    }

    // conv role: pixel px, channel group kq (3 channels)
    const int px = tid % PX_, kq = tid / PX_;
    const int row0 = px / 20, col0 = px % 20;
    const int xoff = row0 * 22 + col0;

    // sig role: pixel pp, quadrant q
    const int pp = tid >> 2, q = tid & 3;
    const int i0 = (q >> 1) * 8, j0 = (q & 1) * 8;

    // stage x_0 into xs[0], prefetch x_1
    float rv[3] = {0.f, 0.f, 0.f};
#pragma unroll
    for (int l = 0; l < 3; l++) if (gof[l] >= 0) rv[l] = xg[gof[l]];
#pragma unroll
    for (int l = 0; l < 3; l++) if (gof[l] >= 0) xs[0][tid + l * THR_] = rv[l];
    {
        const float* xn = xg + (size_t)NV * HW_;
#pragma unroll
        for (int l = 0; l < 3; l++) if (gof[l] >= 0) rv[l] = xn[gof[l]];
    }
    __syncthreads();   // ws2/wb + xs[0] ready

    const float bi0 = wb[kq * 3], bi1 = wb[kq * 3 + 1], bi2 = wb[kq * 3 + 2];

#define CONV_STEP(XB, FT, TVAL)                                            \
    {                                                                      \
        const float* xrow = (XB) + xoff;                                   \
        float a0 = bi0, a1 = bi1, a2 = bi2;                                \
        _Pragma("unroll")                                                  \
        for (int v = 0; v < 4; v++) {                                      \
            float xv[9];                                                   \
            _Pragma("unroll")                                              \
            for (int dy = 0; dy < 3; dy++)                                 \
                _Pragma("unroll")                                          \
                for (int dx = 0; dx < 3; dx++)                             \
                    xv[dy * 3 + dx] = xrow[v * 88 + dy * 22 + dx];         \
            _Pragma("unroll")                                              \
            for (int c = 0; c < 3; c++) {                                  \
                const float4* wp = (const float4*)(ws2 + (kq * 3 + c) * 48 + v * 12); \
                const float4 w0 = wp[0];                                   \
                const float4 w1 = wp[1];                                   \
                const float w8 = ws2[(kq * 3 + c) * 48 + v * 12 + 8];      \
                float s = xv[0] * w0.x;                                    \
                s = fmaf(xv[1], w0.y, s);                                  \
                s = fmaf(xv[2], w0.z, s);                                  \
                s = fmaf(xv[3], w0.w, s);                                  \
                s = fmaf(xv[4], w1.x, s);                                  \
                s = fmaf(xv[5], w1.y, s);                                  \
                s = fmaf(xv[6], w1.z, s);                                  \
                s = fmaf(xv[7], w1.w, s);                                  \
                s = fmaf(xv[8], w8, s);                                    \
                if (c == 0) a0 += s; else if (c == 1) a1 += s; else a2 += s; \
            }                                                              \
        }                                                                  \
        (FT)[(kq * 3 + 0) * 41 + px] = a0;                                 \
        (FT)[(kq * 3 + 1) * 41 + px] = a1;                                 \
        (FT)[(kq * 3 + 2) * 41 + px] = a2;                                 \
        (FT)[(12 + kq) * 41 + px] = xrow[kq * 88 + 23];                    \
        if (kq == 0) (FT)[16 * 41 + px] = (TVAL);                          \
    }

    // prologue: conv(0) -> feat[0]; stage xs[1]=x1; prefetch x2
    CONV_STEP(xs[0], feat[0], 0.f)
#pragma unroll
    for (int l = 0; l < 3; l++) if (gof[l] >= 0) xs[1][tid + l * THR_] = rv[l];
    {
        const float* xn = xg + (size_t)2 * NV * HW_;
#pragma unroll
        for (int l = 0; l < 3; l++) if (gof[l] >= 0) rv[l] = xn[gof[l]];
    }
    __syncthreads();   // feat[0] + xs[1] ready

    float acc[9][9];
#pragma unroll
    for (int a = 0; a < 9; a++)
#pragma unroll
        for (int c = 0; c < 9; c++) acc[a][c] = 0.f;
    // snapshot p0 (needed for epilogue correction)
    for (int i = tid; i < 17 * 41; i += THR_) p0s[i] = feat[0][i];

    int bm1 = 0;   // (k-1)%3
    for (int k = 1; k < T_; k++) {
        const int buf = k % 3;
        float* ft = feat[buf];
        const float* fprev = feat[bm1];
        const float* xb = xs[k & 1];

        // stage x_{k+1} into other xs buffer; prefetch x_{k+2} (clamped)
#pragma unroll
        for (int l = 0; l < 3; l++)
            if (gof[l] >= 0) xs[(k & 1) ^ 1][tid + l * THR_] = rv[l];
        {
            const int tn = (k + 2 < T_) ? (k + 2) : (T_ - 1);
            const float* xn = xg + (size_t)tn * NV * HW_;
#pragma unroll
            for (int l = 0; l < 3; l++) if (gof[l] >= 0) rv[l] = xn[gof[l]];
        }

        // conv(k): xs[k&1] (staged at k-1, bar-protected) -> feat[k%3]
        CONV_STEP(xb, ft, (float)k * (1.0f / 95.0f))

        __syncthreads();   // the ONLY bar per t

        // sig(k): d/m read from cur+prev buffers (no register state)
        float d[9];
#pragma unroll
        for (int c = 0; c < 9; c++)
            d[c] = ft[(j0 + c) * 41 + pp] - fprev[(j0 + c) * 41 + pp];
#pragma unroll
        for (int a = 0; a < 9; a++) {
            const float m = ft[(i0 + a) * 41 + pp] + fprev[(i0 + a) * 41 + pp];
#pragma unroll
            for (int c = 0; c < 9; c++)
                acc[a][c] = fmaf(m, d[c], acc[a][c]);
        }
        bm1 = buf;
    }
#undef CONV_STEP

    // epilogue: p95 from last buffer, p0 from snapshot
    const float* flast = feat[(T_ - 1) % 3];
    float p0i[9], l1[9];
#pragma unroll
    for (int a = 0; a < 9; a++) p0i[a] = p0s[(i0 + a) * 41 + pp];
#pragma unroll
    for (int c = 0; c < 9; c++)
        l1[c] = flast[(j0 + c) * 41 + pp] - p0s[(j0 + c) * 41 + pp];

    float* sg = g_sig + ((size_t)b * HW_ + pbase + pp) * SIGLEN_;
    if (q < 2) {
#pragma unroll
        for (int c = 0; c < 9; c++) sg[j0 + c] = l1[c];
    }
#pragma unroll
    for (int a = 0; a < 9; a++)
#pragma unroll
        for (int c = 0; c < 9; c++)
            sg[17 + (i0 + a) * 17 + (j0 + c)] = 0.5f * acc[a][c] - p0i[a] * l1[c];
}

// ---------------------------------------------------------------------------
// Layer-1 GEMM partials over K=122400, 255 chunks of 480. Reg prefetch.
// ---------------------------------------------------------------------------
__global__ __launch_bounds__(256)
void mlp1_kernel(const float* __restrict__ w1)
{
    __shared__ __align__(16) float ss[32 * 66];
    __shared__ __align__(16) float wsm[32 * 32];

    const int cx = blockIdx.x, tid = threadIdx.x;
    const int oq = tid & 7, bq = tid >> 3;
    const int b0 = bq * 2, o0 = oq * 4;
    const int kb = cx * KC_;

    float ps[8], pw[4];
    {
        const int k0 = kb;
#pragma unroll
        for (int r = 0; r < 8; r++) {
            const int idx = tid + r * 256;
            ps[r] = g_sig[(size_t)(idx >> 5) * KTOT_ + k0 + (idx & 31)];
        }
#pragma unroll
        for (int r = 0; r < 4; r++) {
            const int idx = tid + r * 256;
            pw[r] = w1[(size_t)(k0 + (idx >> 5)) * 32 + (idx & 31)];
        }
    }

    float acc[2][4] = {};

    for (int tile = 0; tile < KC_ / 32; tile++) {
#pragma unroll
        for (int r = 0; r < 8; r++) {
            const int idx = tid + r * 256;
            ss[(idx & 31) * 66 + (idx >> 5)] = ps[r];
        }
#pragma unroll
        for (int r = 0; r < 4; r++) {
            const int idx = tid + r * 256;
            wsm[(idx >> 5) * 32 + (idx & 31)] = pw[r];
        }
        if (tile < KC_ / 32 - 1) {
            const int k0 = kb + (tile + 1) * 32;
#pragma unroll
            for (int r = 0; r < 8; r++) {
                const int idx = tid + r * 256;
                ps[r] = g_sig[(size_t)(idx >> 5) * KTOT_ + k0 + (idx & 31)];
            }
#pragma unroll
            for (int r = 0; r < 4; r++) {
                const int idx = tid + r * 256;
                pw[r] = w1[(size_t)(k0 + (idx >> 5)) * 32 + (idx & 31)];
            }
        }
        __syncthreads();
#pragma unroll
        for (int kk = 0; kk < 32; kk++) {
            const float2 sv = *(const float2*)&ss[kk * 66 + b0];
            const float4 wv = *(const float4*)&wsm[kk * 32 + o0];
            acc[0][0] = fmaf(sv.x, wv.x, acc[0][0]);
            acc[0][1] = fmaf(sv.x, wv.y, acc[0][1]);
            acc[0][2] = fmaf(sv.x, wv.z, acc[0][2]);
            acc[0][3] = fmaf(sv.x, wv.w, acc[0][3]);
            acc[1][0] = fmaf(sv.y, wv.x, acc[1][0]);
            acc[1][1] = fmaf(sv.y, wv.y, acc[1][1]);
            acc[1][2] = fmaf(sv.y, wv.z, acc[1][2]);
            acc[1][3] = fmaf(sv.y, wv.w, acc[1][3]);
        }
        __syncthreads();
    }
#pragma unroll
    for (int i = 0; i < 2; i++)
#pragma unroll
        for (int j = 0; j < 4; j++)
            g_part[((size_t)cx * 64 + b0 + i) * 32 + o0 + j] = acc[i][j];
}

// ---------------------------------------------------------------------------
// Reduce partials + bias/relu + layers 2..4.
// ---------------------------------------------------------------------------
__global__ __launch_bounds__(256)
void mlp_tail_kernel(const float* __restrict__ b1,
                     const float* __restrict__ w2, const float* __restrict__ b2,
                     const float* __restrict__ w3, const float* __restrict__ b3,
                     const float* __restrict__ w4, const float* __restrict__ b4,
                     float* __restrict__ out)
{
    __shared__ float red[8][33];
    const int b = blockIdx.x, tid = threadIdx.x;
    const int o = tid & 31, g = tid >> 5;

    float s = 0.f;
    for (int c = g; c < NCHUNK_; c += 8)
        s += g_part[((size_t)c * 64 + b) * 32 + o];
    red[g][o] = s;
    __syncthreads();

    if (tid < 32) {
        float s1 = b1[o];
#pragma unroll
        for (int gg = 0; gg < 8; gg++) s1 += red[gg][o];
        float h = fmaxf(s1, 0.f);

        float s2 = b2[o];
#pragma unroll
        for (int k = 0; k < 32; k++)
            s2 = fmaf(__shfl_sync(0xffffffffu, h, k), w2[k * 32 + o], s2);
        h = fmaxf(s2, 0.f);

        float s3 = b3[o];
#pragma unroll
        for (int k = 0; k < 32; k++)
            s3 = fmaf(__shfl_sync(0xffffffffu, h, k), w3[k * 32 + o], s3);
        h = fmaxf(s3, 0.f);

        float v = h * w4[o];
#pragma unroll
        for (int off = 16; off; off >>= 1) v += __shfl_xor_sync(0xffffffffu, v, off);
        if (o == 0) out[b] = v + b4[0];
    }
}

// ---------------------------------------------------------------------------
extern "C" void kernel_launch(void* const* d_in, const int* in_sizes, int n_in,
                              void* d_out, int out_size)
{
    const float* x  = (const float*)d_in[0];
    const float* cw = (const float*)d_in[1];
    const float* cb = (const float*)d_in[2];
    const float* w1 = (const float*)d_in[3];
    const float* b1 = (const float*)d_in[4];
    const float* w2 = (const float*)d_in[5];
    const float* b2 = (const float*)d_in[6];
    const float* w3 = (const float*)d_in[7];
    const float* b3 = (const float*)d_in[8];
    const float* w4 = (const float*)d_in[9];
    const float* b4 = (const float*)d_in[10];
    float* out = (float*)d_out;

    fused_conv_sig_kernel<<<dim3(NSTRIP_, B_), THR_>>>(x, cw, cb);
    mlp1_kernel<<<NCHUNK_, 256>>>(w1);
    mlp_tail_kernel<<<B_, 256>>>(b1, w2, b2, w3, b3, w4, b4, out);
}

// round 11
// speedup vs baseline: 2.5195x; 1.1586x over previous
#include <cuda_runtime.h>
#include <cstdint>

#define B_ 64
#define T_ 96
#define NV 4
#define NF_ 17
#define HW_ 400
#define SIGLEN_ 306
#define KTOT_ 122400        // HW_*SIGLEN_
#define NCHUNK_ 255
#define KC_ 480             // NCHUNK_*KC_ == KTOT_

#define NPX_ 32             // pixels per block
#define THR_ 128            // 4 warps: warp = sig quadrant = conv channel group
#define NBLK_ 13            // ceil(400/32), last block half-masked
#define XSZ_ 440            // halo: 4 vars x 5 rows x 22 cols
#define FP_ 33              // feat tile row pitch

__device__ float g_sig [(size_t)B_ * HW_ * SIGLEN_];    // [b][p][s]
__device__ float g_part[(size_t)NCHUNK_ * 64 * 32];

// ---------------------------------------------------------------------------
// Antisymmetric signature step for quadrant Q (offsets 2Q+1, 2Q+2):
// load cur (17 LDS), then A[a][e] += prev_a*cur_b - cur_a*prev_b for
// b = (a + 2Q+1+e) mod 17. All indices compile-time.
// ---------------------------------------------------------------------------
template<int Q>
__device__ __forceinline__ void sig_step(const float* __restrict__ ft, int pp,
                                         float (&cu)[17], const float (&pv)[17],
                                         float (&acc)[34])
{
#pragma unroll
    for (int f = 0; f < 17; f++) cu[f] = ft[f * FP_ + pp];
#pragma unroll
    for (int a = 0; a < 17; a++) {
        const int b0 = (a + 2 * Q + 1) % 17;
        const int b1 = (a + 2 * Q + 2) % 17;
        float t0 = fmaf(pv[a], cu[b0], acc[2 * a]);
        acc[2 * a]     = fmaf(-cu[a], pv[b0], t0);
        float t1 = fmaf(pv[a], cu[b1], acc[2 * a + 1]);
        acc[2 * a + 1] = fmaf(-cu[a], pv[b1], t1);
    }
}

// lvl2_ab = 0.5*W + 0.5*l1_a*l1_b,  lvl2_ba = 0.5*l1_a*l1_b - 0.5*W,
// W = A_ab + p95_a*p0_b - p0_a*p95_b.  Q==0 also writes lvl1 + diagonal.
template<int Q>
__device__ __forceinline__ void sig_epilogue(float* __restrict__ sg,
                                             const float (&p95)[17],
                                             const float* __restrict__ p0s, int pp,
                                             const float (&acc)[34], bool valid)
{
    float p0v[17], l1[17];
#pragma unroll
    for (int f = 0; f < 17; f++) {
        p0v[f] = p0s[f * FP_ + pp];
        l1[f] = p95[f] - p0v[f];
    }
    if (!valid) return;
    if (Q == 0) {
#pragma unroll
        for (int f = 0; f < 17; f++) {
            sg[f] = l1[f];
            sg[17 + f * 17 + f] = 0.5f * l1[f] * l1[f];
        }
    }
#pragma unroll
    for (int a = 0; a < 17; a++) {
#pragma unroll
        for (int e = 0; e < 2; e++) {
            const int b = (a + 2 * Q + 1 + e) % 17;
            const float W = acc[2 * a + e] + p95[a] * p0v[b] - p0v[a] * p95[b];
            const float S = 0.5f * l1[a] * l1[b];
            const float D = 0.5f * W;
            sg[17 + a * 17 + b] = S + D;
            sg[17 + b * 17 + a] = S - D;
        }
    }
}

// ---------------------------------------------------------------------------
// Fused conv3x3(4->12) + feature assembly + antisymmetric path signature.
// Grid (13, 64): block = 32 consecutive raster pixels, 128 threads.
// warp w: conv channels 3w..3w+2 of pixel=lane; sig quadrant Q=w (uniform
// per warp -> no divergence). One __syncthreads per t; xs/feat double buf.
// prev features live in ping-pong register arrays (cuA/cuB).
// ---------------------------------------------------------------------------
__global__ __launch_bounds__(THR_, 4)
void fused_conv_sig_kernel(const float* __restrict__ x,
                           const float* __restrict__ cw,
                           const float* __restrict__ cb)
{
    __shared__ __align__(16) float xs[2][XSZ_];       // halo 4v x 5rows x 22
    __shared__ __align__(16) float ws2[12 * 48];      // weights [k][v][12pad]
    __shared__ float wb[12];
    __shared__ __align__(16) float feat[2][17 * FP_];
    __shared__ float p0s[17 * FP_];

    const int bxi = blockIdx.x;          // 0..12
    const int b   = blockIdx.y;
    const int tid = threadIdx.x;
    const int lane = tid & 31;
    const int wq   = tid >> 5;           // warp id = quadrant = channel group
    const int pbase = bxi * NPX_;
    const bool valid = (pbase + lane) < HW_;
    const int pxg = valid ? (pbase + lane) : (HW_ - 1);
    const int r0 = pbase / 20;

    // init smem: zero xs buffers (halo guards stay 0), repack weights
    for (int i = tid; i < 2 * XSZ_; i += THR_) (&xs[0][0])[i] = 0.f;
    for (int i = tid; i < 432; i += THR_) {
        const int k = i / 36, r = i % 36, v = r / 9, tap = r % 9;
        ws2[k * 48 + v * 12 + tap] = cw[i];
    }
    if (tid < 12) wb[tid] = cb[tid];

    // x-staging offsets, 4 legs
    const float* xg = x + (size_t)b * T_ * NV * HW_;
    int gof[4];
#pragma unroll
    for (int l = 0; l < 4; l++) {
        const int i = tid + l * THR_;
        gof[l] = -1;
        if (i < XSZ_) {
            const int v = i / 110, r = i % 110, rr = r / 22, col = r % 22;
            const int gr = r0 - 1 + rr;
            if (gr >= 0 && gr < 20 && col >= 1 && col <= 20)
                gof[l] = v * HW_ + gr * 20 + (col - 1);
        }
    }

    const int prow = pxg / 20 - r0;      // 0..2 within halo
    const int pcol = pxg % 20;
    const int xoff = prow * 22 + pcol;
    const int k0ch = 3 * wq;

    // stage x_0 into xs[0], prefetch x_1
    float rv[4] = {0.f, 0.f, 0.f, 0.f};
#pragma unroll
    for (int l = 0; l < 4; l++) if (gof[l] >= 0) rv[l] = xg[gof[l]];
#pragma unroll
    for (int l = 0; l < 4; l++) if (gof[l] >= 0) xs[0][tid + l * THR_] = rv[l];
    {
        const float* xn = xg + (size_t)NV * HW_;
#pragma unroll
        for (int l = 0; l < 4; l++) if (gof[l] >= 0) rv[l] = xn[gof[l]];
    }
    __syncthreads();   // ws2/wb + xs[0] ready

    const float bi0 = wb[k0ch], bi1 = wb[k0ch + 1], bi2 = wb[k0ch + 2];

#define CONV_STEP(XB, FT, TVAL)                                            \
    {                                                                      \
        const float* xrow = (XB) + xoff;                                   \
        float a0 = bi0, a1 = bi1, a2 = bi2;                                \
        _Pragma("unroll")                                                  \
        for (int v = 0; v < 4; v++) {                                      \
            float xv[9];                                                   \
            _Pragma("unroll")                                              \
            for (int dy = 0; dy < 3; dy++)                                 \
                _Pragma("unroll")                                          \
                for (int dx = 0; dx < 3; dx++)                             \
                    xv[dy * 3 + dx] = xrow[v * 110 + dy * 22 + dx];        \
            _Pragma("unroll")                                              \
            for (int c = 0; c < 3; c++) {                                  \
                const float4* wp = (const float4*)(ws2 + (k0ch + c) * 48 + v * 12); \
                const float4 w0 = wp[0];                                   \
                const float4 w1 = wp[1];                                   \
                const float w8 = ws2[(k0ch + c) * 48 + v * 12 + 8];        \
                float s = xv[0] * w0.x;                                    \
                s = fmaf(xv[1], w0.y, s);                                  \
                s = fmaf(xv[2], w0.z, s);                                  \
                s = fmaf(xv[3], w0.w, s);                                  \
                s = fmaf(xv[4], w1.x, s);                                  \
                s = fmaf(xv[5], w1.y, s);                                  \
                s = fmaf(xv[6], w1.z, s);                                  \
                s = fmaf(xv[7], w1.w, s);                                  \
                s = fmaf(xv[8], w8, s);                                    \
                if (c == 0) a0 += s; else if (c == 1) a1 += s; else a2 += s; \
            }                                                              \
        }                                                                  \
        (FT)[(k0ch + 0) * FP_ + lane] = a0;                                \
        (FT)[(k0ch + 1) * FP_ + lane] = a1;                                \
        (FT)[(k0ch + 2) * FP_ + lane] = a2;                                \
        (FT)[(12 + wq) * FP_ + lane] = xrow[wq * 110 + 23];                \
        if (wq == 0) (FT)[16 * FP_ + lane] = (TVAL);                       \
    }

#define SIG_SWITCH(FT, CUR, PRV)                                           \
    switch (wq) {                                                          \
        case 0:  sig_step<0>((FT), lane, (CUR), (PRV), acc); break;        \
        case 1:  sig_step<1>((FT), lane, (CUR), (PRV), acc); break;        \
        case 2:  sig_step<2>((FT), lane, (CUR), (PRV), acc); break;        \
        default: sig_step<3>((FT), lane, (CUR), (PRV), acc); break;        \
    }

    // prologue: conv(0) -> feat[0]; stage xs[1]=x1; prefetch x2
    CONV_STEP(xs[0], feat[0], 0.f)
#pragma unroll
    for (int l = 0; l < 4; l++) if (gof[l] >= 0) xs[1][tid + l * THR_] = rv[l];
    {
        const float* xn = xg + (size_t)2 * NV * HW_;
#pragma unroll
        for (int l = 0; l < 4; l++) if (gof[l] >= 0) rv[l] = xn[gof[l]];
    }
    __syncthreads();   // feat[0] + xs[1] ready

    float cuA[17], cuB[17], acc[34];
#pragma unroll
    for (int i = 0; i < 34; i++) acc[i] = 0.f;
#pragma unroll
    for (int f = 0; f < 17; f++) cuA[f] = feat[0][f * FP_ + lane];   // p_0
    for (int i = tid; i < 17 * FP_; i += THR_) p0s[i] = feat[0][i];  // pre-bar3: safe

    // main loop: k = 1..95, two steps per iteration (ping-pong cuA/cuB)
    for (int kk = 0; kk < 48; kk++) {
        const int k = 2 * kk + 1;          // odd step: cur -> cuB
        {
#pragma unroll
            for (int l = 0; l < 4; l++) if (gof[l] >= 0) xs[0][tid + l * THR_] = rv[l];
            const int tn = (k + 2 < T_) ? k + 2 : T_ - 1;
            const float* xn = xg + (size_t)tn * NV * HW_;
#pragma unroll
            for (int l = 0; l < 4; l++) if (gof[l] >= 0) rv[l] = xn[gof[l]];
            CONV_STEP(xs[1], feat[1], (float)k * (1.0f / 95.0f))
            __syncthreads();
            SIG_SWITCH(feat[1], cuB, cuA)
        }
        if (kk < 47) {
            const int k2 = k + 1;          // even step: cur -> cuA
#pragma unroll
            for (int l = 0; l < 4; l++) if (gof[l] >= 0) xs[1][tid + l * THR_] = rv[l];
            const int tn = (k2 + 2 < T_) ? k2 + 2 : T_ - 1;
            const float* xn = xg + (size_t)tn * NV * HW_;
#pragma unroll
            for (int l = 0; l < 4; l++) if (gof[l] >= 0) rv[l] = xn[gof[l]];
            CONV_STEP(xs[0], feat[0], (float)k2 * (1.0f / 95.0f))
            __syncthreads();
            SIG_SWITCH(feat[0], cuA, cuB)
        }
    }
#undef CONV_STEP
#undef SIG_SWITCH

    // epilogue: p95 = cuB (k=95 odd), p0 from snapshot
    float* sg = g_sig + ((size_t)b * HW_ + pxg) * SIGLEN_;
    switch (wq) {
        case 0:  sig_epilogue<0>(sg, cuB, p0s, lane, acc, valid); break;
        case 1:  sig_epilogue<1>(sg, cuB, p0s, lane, acc, valid); break;
        case 2:  sig_epilogue<2>(sg, cuB, p0s, lane, acc, valid); break;
        default: sig_epilogue<3>(sg, cuB, p0s, lane, acc, valid); break;
    }
}

// ---------------------------------------------------------------------------
// Layer-1 GEMM partials over K=122400, 255 chunks of 480. Reg prefetch.
// ---------------------------------------------------------------------------
__global__ __launch_bounds__(256)
void mlp1_kernel(const float* __restrict__ w1)
{
    __shared__ __align__(16) float ss[32 * 66];
    __shared__ __align__(16) float wsm[32 * 32];

    const int cx = blockIdx.x, tid = threadIdx.x;
    const int oq = tid & 7, bq = tid >> 3;
    const int b0 = bq * 2, o0 = oq * 4;
    const int kb = cx * KC_;

    float ps[8], pw[4];
    {
        const int k0 = kb;
#pragma unroll
        for (int r = 0; r < 8; r++) {
            const int idx = tid + r * 256;
            ps[r] = g_sig[(size_t)(idx >> 5) * KTOT_ + k0 + (idx & 31)];
        }
#pragma unroll
        for (int r = 0; r < 4; r++) {
            const int idx = tid + r * 256;
            pw[r] = w1[(size_t)(k0 + (idx >> 5)) * 32 + (idx & 31)];
        }
    }

    float acc[2][4] = {};

    for (int tile = 0; tile < KC_ / 32; tile++) {
#pragma unroll
        for (int r = 0; r < 8; r++) {
            const int idx = tid + r * 256;
            ss[(idx & 31) * 66 + (idx >> 5)] = ps[r];
        }
#pragma unroll
        for (int r = 0; r < 4; r++) {
            const int idx = tid + r * 256;
            wsm[(idx >> 5) * 32 + (idx & 31)] = pw[r];
        }
        if (tile < KC_ / 32 - 1) {
            const int k0 = kb + (tile + 1) * 32;
#pragma unroll
            for (int r = 0; r < 8; r++) {
                const int idx = tid + r * 256;
                ps[r] = g_sig[(size_t)(idx >> 5) * KTOT_ + k0 + (idx & 31)];
            }
#pragma unroll
            for (int r = 0; r < 4; r++) {
                const int idx = tid + r * 256;
                pw[r] = w1[(size_t)(k0 + (idx >> 5)) * 32 + (idx & 31)];
            }
        }
        __syncthreads();
#pragma unroll
        for (int kk = 0; kk < 32; kk++) {
            const float2 sv = *(const float2*)&ss[kk * 66 + b0];
            const float4 wv = *(const float4*)&wsm[kk * 32 + o0];
            acc[0][0] = fmaf(sv.x, wv.x, acc[0][0]);
            acc[0][1] = fmaf(sv.x, wv.y, acc[0][1]);
            acc[0][2] = fmaf(sv.x, wv.z, acc[0][2]);
            acc[0][3] = fmaf(sv.x, wv.w, acc[0][3]);
            acc[1][0] = fmaf(sv.y, wv.x, acc[1][0]);
            acc[1][1] = fmaf(sv.y, wv.y, acc[1][1]);
            acc[1][2] = fmaf(sv.y, wv.z, acc[1][2]);
            acc[1][3] = fmaf(sv.y, wv.w, acc[1][3]);
        }
        __syncthreads();
    }
#pragma unroll
    for (int i = 0; i < 2; i++)
#pragma unroll
        for (int j = 0; j < 4; j++)
            g_part[((size_t)cx * 64 + b0 + i) * 32 + o0 + j] = acc[i][j];
}

// ---------------------------------------------------------------------------
// Reduce partials + bias/relu + layers 2..4.
// ---------------------------------------------------------------------------
__global__ __launch_bounds__(256)
void mlp_tail_kernel(const float* __restrict__ b1,
                     const float* __restrict__ w2, const float* __restrict__ b2,
                     const float* __restrict__ w3, const float* __restrict__ b3,
                     const float* __restrict__ w4, const float* __restrict__ b4,
                     float* __restrict__ out)
{
    __shared__ float red[8][33];
    const int b = blockIdx.x, tid = threadIdx.x;
    const int o = tid & 31, g = tid >> 5;

    float s = 0.f;
    for (int c = g; c < NCHUNK_; c += 8)
        s += g_part[((size_t)c * 64 + b) * 32 + o];
    red[g][o] = s;
    __syncthreads();

    if (tid < 32) {
        float s1 = b1[o];
#pragma unroll
        for (int gg = 0; gg < 8; gg++) s1 += red[gg][o];
        float h = fmaxf(s1, 0.f);

        float s2 = b2[o];
#pragma unroll
        for (int k = 0; k < 32; k++)
            s2 = fmaf(__shfl_sync(0xffffffffu, h, k), w2[k * 32 + o], s2);
        h = fmaxf(s2, 0.f);

        float s3 = b3[o];
#pragma unroll
        for (int k = 0; k < 32; k++)
            s3 = fmaf(__shfl_sync(0xffffffffu, h, k), w3[k * 32 + o], s3);
        h = fmaxf(s3, 0.f);

        float v = h * w4[o];
#pragma unroll
        for (int off = 16; off; off >>= 1) v += __shfl_xor_sync(0xffffffffu, v, off);
        if (o == 0) out[b] = v + b4[0];
    }
}

// ---------------------------------------------------------------------------
extern "C" void kernel_launch(void* const* d_in, const int* in_sizes, int n_in,
                              void* d_out, int out_size)
{
    const float* x  = (const float*)d_in[0];
    const float* cw = (const float*)d_in[1];
    const float* cb = (const float*)d_in[2];
    const float* w1 = (const float*)d_in[3];
    const float* b1 = (const float*)d_in[4];
    const float* w2 = (const float*)d_in[5];
    const float* b2 = (const float*)d_in[6];
    const float* w3 = (const float*)d_in[7];
    const float* b3 = (const float*)d_in[8];
    const float* w4 = (const float*)d_in[9];
    const float* b4 = (const float*)d_in[10];
    float* out = (float*)d_out;

    fused_conv_sig_kernel<<<dim3(NBLK_, B_), THR_>>>(x, cw, cb);
    mlp1_kernel<<<NCHUNK_, 256>>>(w1);
    mlp_tail_kernel<<<B_, 256>>>(b1, w2, b2, w3, b3, w4, b4, out);
}